// round 4
// baseline (speedup 1.0000x reference)
#include <cuda_runtime.h>
#include <cstdint>

// out[dst] += x[src] for each edge, D_FEAT = 64 fp32.
// Indices are int32 (JAX without x64 downcasts int64 -> int32).
// One thread per (edge, 16B chunk): 16 threads cover one edge's 64 floats.
// Vector reduction red.global.add.v4.f32 (sm_90+) -> 1 LTS atomic per 16B.

#define D_FEAT 64
#define CHUNKS 16   // 64 floats / 4 per float4

__global__ void scatter_add_kernel(const float4* __restrict__ x4,
                                   const int* __restrict__ src_idx,
                                   const int* __restrict__ dst_idx,
                                   float* __restrict__ out,
                                   int n_edges, int n_nodes)
{
    long long tid = (long long)blockIdx.x * blockDim.x + threadIdx.x;
    long long edge = tid >> 4;          // 16 threads per edge
    int chunk = (int)(tid & 15);
    if (edge >= n_edges) return;

    // 16 consecutive lanes read the same index -> one sector, L1 broadcast
    int s = __ldg(src_idx + edge);
    int d = __ldg(dst_idx + edge);

    // Never fires with valid inputs; insurance against layout surprises.
    if ((unsigned)s >= (unsigned)n_nodes || (unsigned)d >= (unsigned)n_nodes) return;

    float4 v = __ldg(x4 + (size_t)s * CHUNKS + chunk);

    float* dst_ptr = out + (size_t)d * D_FEAT + (size_t)chunk * 4;
    asm volatile("red.global.add.v4.f32 [%0], {%1, %2, %3, %4};"
                 :: "l"(dst_ptr), "f"(v.x), "f"(v.y), "f"(v.z), "f"(v.w)
                 : "memory");
}

extern "C" void kernel_launch(void* const* d_in, const int* in_sizes, int n_in,
                              void* d_out, int out_size)
{
    // Role detection by element count:
    //   x:          6,400,000 fp32 elements
    //   edge_index: 2,500,000 int32 elements
    int xi = 0, ei = 1;
    if (n_in >= 2 && in_sizes[1] > in_sizes[0]) { xi = 1; ei = 0; }

    const float4* x4 = (const float4*)d_in[xi];
    const int* edge_index = (const int*)d_in[ei];

    int n_edges = in_sizes[ei] / 2;
    int n_nodes = in_sizes[xi] / D_FEAT;

    const int* src_idx = edge_index;            // row 0
    const int* dst_idx = edge_index + n_edges;  // row 1

    float* out = (float*)d_out;

    // Output is poisoned 0xAA -> zero it first (capturable memset)
    cudaMemsetAsync(out, 0, (size_t)out_size * sizeof(float));

    long long total = (long long)n_edges * CHUNKS;
    int threads = 256;
    int blocks = (int)((total + threads - 1) / threads);
    scatter_add_kernel<<<blocks, threads>>>(x4, src_idx, dst_idx, out, n_edges, n_nodes);
}